// round 12
// baseline (speedup 1.0000x reference)
#include <cuda_runtime.h>
#include <math.h>
#include <stdint.h>

#define VOCAB    32000
#define V4       8000                // float4 per row
#define NROWS    4092                // 4 * 1023
#define SEQ      1024
#define TPB      512
#define MAXCTA   256

#define LQ       12                  // LDG quads per thread (quads 0..6143)
#define LQBASE   (LQ * TPB)          // 6144 = first TMA quad
#define TQ       (V4 - LQBASE)       // 1856 TMA quads per row
#define TAILT    (TQ - 3 * TPB)      // 320 (= 10 full warps)
#define TMA_B    (TQ * 16)           // 29696 bytes
#define TH_BYTES (VOCAB * 4)         // 128000
#define DYN_SMEM (TH_BYTES + 2 * TMA_B)   // 187392

__device__ double   g_part[MAXCTA];
__device__ unsigned g_cnt = 0;

// ---------- mbarrier / bulk-async ----------
__device__ __forceinline__ uint32_t smem_u32(const void* p) {
    uint32_t a;
    asm("{ .reg .u64 t; cvta.to.shared.u64 t, %1; cvt.u32.u64 %0, t; }" : "=r"(a) : "l"(p));
    return a;
}
__device__ __forceinline__ void mbar_init(uint32_t mbar, uint32_t cnt) {
    asm volatile("mbarrier.init.shared.b64 [%0], %1;" :: "r"(mbar), "r"(cnt) : "memory");
}
__device__ __forceinline__ void mbar_expect_tx(uint32_t mbar, uint32_t bytes) {
    asm volatile("mbarrier.arrive.expect_tx.shared.b64 _, [%0], %1;" :: "r"(mbar), "r"(bytes) : "memory");
}
__device__ __forceinline__ void mbar_arrive(uint32_t mbar) {
    asm volatile("mbarrier.arrive.shared.b64 _, [%0];" :: "r"(mbar) : "memory");
}
__device__ __forceinline__ void mbar_wait(uint32_t mbar, uint32_t parity) {
    uint32_t done;
    asm volatile(
        "{\n\t.reg .pred p;\n\t"
        "mbarrier.try_wait.parity.acquire.cta.shared::cta.b64 p, [%1], %2;\n\t"
        "selp.b32 %0, 1, 0, p;\n\t}"
        : "=r"(done) : "r"(mbar), "r"(parity) : "memory");
    if (!done) {
        asm volatile(
            "{\n\t.reg .pred P1;\n\t"
            "WL_%=:\n\t"
            "mbarrier.try_wait.parity.acquire.cta.shared::cta.b64 P1, [%0], %1, 0x989680;\n\t"
            "@P1 bra.uni WD_%=;\n\t"
            "bra.uni WL_%=;\n\t"
            "WD_%=:\n\t}"
            :: "r"(mbar), "r"(parity) : "memory");
    }
}
__device__ __forceinline__ void bulk_ld(uint32_t dst, const void* src,
                                        uint32_t bytes, uint32_t mbar) {
    asm volatile(
        "cp.async.bulk.shared::cluster.global.mbarrier::complete_tx::bytes [%0], [%1], %2, [%3];"
        :: "r"(dst), "l"(src), "r"(bytes), "r"(mbar) : "memory");
}

// raw MUFU.LG2
__device__ __forceinline__ float lg2(float x) {
    float r; asm("lg2.approx.f32 %0, %1;" : "=f"(r) : "f"(x)); return r;
}

// scalar fast log (prologue only)
__device__ __forceinline__ float lnfast(float x) {
    int i = __float_as_int(x);
    int k = (i - 0x3F2AAAAB) & 0xFF800000;
    float f = __int_as_float(i - k) - 1.0f;
    float P = 0.2f;
    P = fmaf(P, f, -0.25f);
    P = fmaf(P, f,  0.33333334f);
    P = fmaf(P, f, -0.5f);
    P = fmaf(P, f,  1.0f);
    return fmaf(f, P, (float)k * 8.2629582e-8f);
}

__device__ __forceinline__ float warp_sum(float v) {
    #pragma unroll
    for (int o = 16; o; o >>= 1) v += __shfl_xor_sync(0xFFFFFFFFu, v, o);
    return v;
}
__device__ __forceinline__ double warp_sum_d(double v) {
    #pragma unroll
    for (int o = 16; o; o >>= 1) v += __shfl_xor_sync(0xFFFFFFFFu, v, o);
    return v;
}

__device__ __forceinline__ void proc_quad(float4 v, float4 w, float& a0, float& a1) {
    a0 = fmaf(w.x, lg2(v.x), a0);
    a1 = fmaf(w.y, lg2(v.y), a1);
    a0 = fmaf(w.z, lg2(v.z), a0);
    a1 = fmaf(w.w, lg2(v.w), a1);
}

// row -> float offset of row start ( (row + row/1023) * 32000 )
__device__ __forceinline__ size_t row_off(int row) {
    return (size_t)(row + row / 1023) * VOCAB;
}
__device__ __forceinline__ const float4* row_ptr(const float* p, int row) {
    return reinterpret_cast<const float4*>(p + row_off(row));
}

__global__ void __launch_bounds__(TPB, 1)
main_kernel(const float* __restrict__ p,
            const int*   __restrict__ dec,
            const float* __restrict__ th,
            float* __restrict__ out) {
    extern __shared__ float smem_dyn[];
    float* sth  = smem_dyn;                             // 128000 B
    char*  bufs = (char*)smem_dyn + TH_BYTES;           // 2 x 29696 B
    __shared__ float  redf[TPB / 32];
    __shared__ double redd[TPB / 32];
    __shared__ float  s_b[2];
    __shared__ int    s_last;
    __shared__ alignas(8) unsigned long long mb_full[2];
    __shared__ alignas(8) unsigned long long mb_empty[2];

    const int tid = threadIdx.x;
    const int g   = gridDim.x;
    const uint32_t mbF0 = smem_u32(&mb_full[0]);
    const uint32_t mbE0 = smem_u32(&mb_empty[0]);

    float4* sth4 = reinterpret_cast<float4*>(sth);
    const float4* th4 = reinterpret_cast<const float4*>(th);
    if (tid == 0) {
        mbar_init(mbF0,     1);   mbar_init(mbF0 + 8, 1);
        mbar_init(mbE0,   TPB);   mbar_init(mbE0 + 8, TPB);
    }
    for (int i = tid; i < V4; i += TPB) sth4[i] = th4[i];
    __syncthreads();

    // ---- kick off TMA for first two rows (before prologue compute) ----
    int tprow = blockIdx.x;
    if (tid == 0) {
        if (tprow < NROWS) {
            mbar_expect_tx(mbF0, TMA_B);
            bulk_ld(smem_u32(bufs), p + row_off(tprow) + LQBASE * 4, TMA_B, mbF0);
        }
        if (tprow + g < NROWS) {
            mbar_expect_tx(mbF0 + 8, TMA_B);
            bulk_ld(smem_u32(bufs + TMA_B), p + row_off(tprow + g) + LQBASE * 4, TMA_B, mbF0 + 8);
        }
        tprow += 2 * g;   // next TMA row to issue (tid0-local use)
    }

    // ---- prologue: usum ----
    {
        float s = 0.f;
        for (int i = tid; i < VOCAB; i += TPB) s += sth[i];
        s = warp_sum(s);
        if ((tid & 31) == 0) redf[tid >> 5] = s;
        __syncthreads();
        if (tid == 0) {
            float t = 0.f;
            #pragma unroll
            for (int w = 0; w < TPB / 32; w++) t += redf[w];
            s_b[0] = t;
        }
        __syncthreads();
    }
    const float usum  = s_b[0];
    const float inv01 = 0.1f / usum;

    // ---- prologue: C1 = sum f(eps*u_v) ----
    {
        float c = 0.f;
        for (int i = tid; i < VOCAB; i += TPB) {
            float x = sth[i] * inv01;
            c += x * lnfast(x);
        }
        c = warp_sum(c);
        if ((tid & 31) == 0) redf[tid >> 5] = c;
        __syncthreads();
        if (tid == 0) {
            float t = 0.f;
            #pragma unroll
            for (int w = 0; w < TPB / 32; w++) t += redf[w];
            s_b[1] = t;
        }
        __syncthreads();
    }
    const float C1 = s_b[1];

    double accD = 0.0;

    // ---- bulk: hybrid LDG(12q) + TMA(1856q) per row ----
    float thrAcc = 0.f;
    int cur = 0;
    int fp0 = 0, fp1 = 0;        // full-barrier parities (all threads)
    int ep0 = 0, ep1 = 0;        // empty-barrier parities (tid0)

    int row = blockIdx.x;
    if (row < NROWS) {
        const float4* cp = row_ptr(p, row);
        // preload G0 (quads 0..5)
        float4 r0 = cp[tid          ];
        float4 r1 = cp[tid + 1 * TPB];
        float4 r2 = cp[tid + 2 * TPB];
        float4 r3 = cp[tid + 3 * TPB];
        float4 r4 = cp[tid + 4 * TPB];
        float4 r5 = cp[tid + 5 * TPB];

        while (true) {
            const int b   = row / 1023;
            const int lbl = __ldg(&dec[b * SEQ + (row - b * 1023) + 1]);
            const int  nrow  = row + g;
            const bool valid = (nrow < NROWS);
            const float4* np = valid ? row_ptr(p, nrow) : cp;

            float a0 = 0.f, a1 = 0.f;

            // load G1 (quads 6..11)
            float4 s0 = cp[tid +  6 * TPB];
            float4 s1 = cp[tid +  7 * TPB];
            float4 s2 = cp[tid +  8 * TPB];
            float4 s3 = cp[tid +  9 * TPB];
            float4 s4 = cp[tid + 10 * TPB];
            float4 s5 = cp[tid + 11 * TPB];
            // process G0
            proc_quad(r0, sth4[tid          ], a0, a1);
            proc_quad(r1, sth4[tid + 1 * TPB], a0, a1);
            proc_quad(r2, sth4[tid + 2 * TPB], a0, a1);
            proc_quad(r3, sth4[tid + 3 * TPB], a0, a1);
            proc_quad(r4, sth4[tid + 4 * TPB], a0, a1);
            proc_quad(r5, sth4[tid + 5 * TPB], a0, a1);
            // load next row G0
            r0 = np[tid          ];
            r1 = np[tid + 1 * TPB];
            r2 = np[tid + 2 * TPB];
            r3 = np[tid + 3 * TPB];
            r4 = np[tid + 4 * TPB];
            r5 = np[tid + 5 * TPB];
            // process G1
            proc_quad(s0, sth4[tid +  6 * TPB], a0, a1);
            proc_quad(s1, sth4[tid +  7 * TPB], a0, a1);
            proc_quad(s2, sth4[tid +  8 * TPB], a0, a1);
            proc_quad(s3, sth4[tid +  9 * TPB], a0, a1);
            proc_quad(s4, sth4[tid + 10 * TPB], a0, a1);
            proc_quad(s5, sth4[tid + 11 * TPB], a0, a1);

            // ---- TMA part from smem buffer ----
            const uint32_t mbF = mbF0 + (cur << 3);
            mbar_wait(mbF, cur ? fp1 : fp0);
            if (cur) fp1 ^= 1; else fp0 ^= 1;

            const float4* tb = reinterpret_cast<const float4*>(bufs + cur * TMA_B);
            proc_quad(tb[tid          ], sth4[LQBASE + tid          ], a0, a1);
            proc_quad(tb[tid + 1 * TPB], sth4[LQBASE + tid + 1 * TPB], a0, a1);
            proc_quad(tb[tid + 2 * TPB], sth4[LQBASE + tid + 2 * TPB], a0, a1);
            if (tid < TAILT)
                proc_quad(tb[tid + 3 * TPB], sth4[LQBASE + tid + 3 * TPB], a0, a1);

            // release buffer; tid0 refills it with row r+2's TMA part
            const uint32_t mbE = mbE0 + (cur << 3);
            mbar_arrive(mbE);
            if (tid == 0) {
                if (tprow < NROWS) {
                    mbar_wait(mbE, cur ? ep1 : ep0);
                    if (cur) ep1 ^= 1; else ep0 ^= 1;
                    mbar_expect_tx(mbF, TMA_B);
                    bulk_ld(smem_u32(bufs + cur * TMA_B),
                            p + row_off(tprow) + LQBASE * 4, TMA_B, mbF);
                }
                tprow += g;
            }

            if (lbl != 0) thrAcc += a0 + a1;

            if (!valid) break;
            row = nrow;
            cp  = np;
            cur ^= 1;
        }
    }

    // ---- label-dependent O(1)-per-row terms (moved after bulk) ----
    for (int gid = blockIdx.x * TPB + tid; gid < NROWS; gid += g * TPB) {
        const int b = gid / 1023;
        const int t = gid - b * 1023;
        const int l = __ldg(&dec[b * SEQ + t + 1]);
        if (l != 0) {
            float pl = __ldg(p + (size_t)(b * SEQ + t) * VOCAB + l);
            float x  = sth[l] * inv01;
            accD += (double)(C1
                             - x * logf(x)
                             + (x + 0.9f) * logf(x + 0.9f)
                             - 0.9f * logf(pl));
        }
    }

    // fold: accD += -eps/usum * ln2 * thrAcc
    accD += (double)thrAcc * (-0.1 * 0.6931471805599453 / (double)usum);

    // ---- per-CTA reduction ----
    accD = warp_sum_d(accD);
    if ((tid & 31) == 0) redd[tid >> 5] = accD;
    __syncthreads();
    if (tid == 0) {
        double t = 0.0;
        #pragma unroll
        for (int w = 0; w < TPB / 32; w++) t += redd[w];
        g_part[blockIdx.x] = t;
        __threadfence();
        unsigned old = atomicAdd(&g_cnt, 1u);
        s_last = (old == (unsigned)g - 1u) ? 1 : 0;
    }
    __syncthreads();

    // ---- last CTA finalizes ----
    if (s_last) {
        double v = (tid < g) ? g_part[tid] : 0.0;
        v = warp_sum_d(v);
        if ((tid & 31) == 0) redd[tid >> 5] = v;
        __syncthreads();
        if (tid == 0) {
            double t = 0.0;
            #pragma unroll
            for (int w = 0; w < TPB / 32; w++) t += redd[w];
            out[0] = (float)(t / (double)NROWS);
            g_cnt = 0;                 // reset for next graph replay
        }
    }
}

extern "C" void kernel_launch(void* const* d_in, const int* in_sizes, int n_in,
                              void* d_out, int out_size) {
    const int*   dec = nullptr;
    const float* p   = nullptr;
    const float* th  = nullptr;
    for (int i = 0; i < n_in; ++i) {
        if (in_sizes[i] == 4 * SEQ)    dec = (const int*)d_in[i];
        else if (in_sizes[i] == VOCAB) th  = (const float*)d_in[i];
        else                           p   = (const float*)d_in[i];
    }

    cudaFuncSetAttribute(main_kernel,
                         cudaFuncAttributeMaxDynamicSharedMemorySize,
                         DYN_SMEM);

    int sms = 0;
    cudaDeviceGetAttribute(&sms, cudaDevAttrMultiProcessorCount, 0);
    if (sms <= 0) sms = 148;
    if (sms > MAXCTA) sms = MAXCTA;

    main_kernel<<<sms, TPB, DYN_SMEM>>>(p, dec, th, (float*)d_out);
}

// round 13
// speedup vs baseline: 1.0681x; 1.0681x over previous
#include <cuda_runtime.h>
#include <math.h>

#define VOCAB   32000
#define V4      8000                 // float4 per row
#define NROWS   4092                 // 4 * 1023
#define SEQ     1024
#define TPB     1024
#define TAILQ   (V4 - 7 * TPB)       // 832 tail quads (= 26 full warps)
#define MAXCTA  256

__device__ double   g_part[MAXCTA];
__device__ unsigned g_cnt = 0;

// raw MUFU.LG2 (full-range log2 approx, single instruction)
__device__ __forceinline__ float lg2(float x) {
    float r; asm("lg2.approx.f32 %0, %1;" : "=f"(r) : "f"(x)); return r;
}

// streaming (evict-first) 128-bit load
__device__ __forceinline__ float4 ldcs4(const float4* a) {
    return __ldcs(a);
}

// scalar fast log (prologue only): degree-5, |abs err| <= 2e-4
__device__ __forceinline__ float lnfast(float x) {
    int i = __float_as_int(x);
    int k = (i - 0x3F2AAAAB) & 0xFF800000;
    float f = __int_as_float(i - k) - 1.0f;
    float P = 0.2f;
    P = fmaf(P, f, -0.25f);
    P = fmaf(P, f,  0.33333334f);
    P = fmaf(P, f, -0.5f);
    P = fmaf(P, f,  1.0f);
    return fmaf(f, P, (float)k * 8.2629582e-8f);
}

__device__ __forceinline__ float warp_sum(float v) {
    #pragma unroll
    for (int o = 16; o; o >>= 1) v += __shfl_xor_sync(0xFFFFFFFFu, v, o);
    return v;
}
__device__ __forceinline__ double warp_sum_d(double v) {
    #pragma unroll
    for (int o = 16; o; o >>= 1) v += __shfl_xor_sync(0xFFFFFFFFu, v, o);
    return v;
}

// one quad: 2-accumulator form
__device__ __forceinline__ void proc_quad(float4 v, float4 w, float& a0, float& a1) {
    a0 = fmaf(w.x, lg2(v.x), a0);
    a1 = fmaf(w.y, lg2(v.y), a1);
    a0 = fmaf(w.z, lg2(v.z), a0);
    a1 = fmaf(w.w, lg2(v.w), a1);
}

// row -> base quad pointer ( b*1024 + t = row + row/1023 )
__device__ __forceinline__ const float4* row_ptr(const float* p, int row) {
    int off = row + row / 1023;
    return reinterpret_cast<const float4*>(p + (size_t)off * VOCAB);
}

__global__ void __launch_bounds__(TPB, 1)
main_kernel(const float* __restrict__ p,
            const int*   __restrict__ dec,
            const float* __restrict__ th,
            float* __restrict__ out) {
    extern __shared__ float sth[];               // 32000 floats = 128 KB
    __shared__ float  redf[TPB / 32];
    __shared__ double redd[TPB / 32];
    __shared__ float  s_b[2];
    __shared__ int    s_last;

    const int tid = threadIdx.x;
    float4* sth4 = reinterpret_cast<float4*>(sth);
    const float4* th4 = reinterpret_cast<const float4*>(th);
    for (int i = tid; i < V4; i += TPB) sth4[i] = th4[i];
    __syncthreads();

    // ---- prologue: usum ----
    {
        float s = 0.f;
        for (int i = tid; i < VOCAB; i += TPB) s += sth[i];
        s = warp_sum(s);
        if ((tid & 31) == 0) redf[tid >> 5] = s;
        __syncthreads();
        if (tid == 0) {
            float t = 0.f;
            #pragma unroll
            for (int w = 0; w < TPB / 32; w++) t += redf[w];
            s_b[0] = t;
        }
        __syncthreads();
    }
    const float usum  = s_b[0];
    const float inv01 = 0.1f / usum;

    // ---- prologue: C1 = sum f(eps*u_v) ----
    {
        float c = 0.f;
        for (int i = tid; i < VOCAB; i += TPB) {
            float x = sth[i] * inv01;
            c += x * lnfast(x);
        }
        c = warp_sum(c);
        if ((tid & 31) == 0) redf[tid >> 5] = c;
        __syncthreads();
        if (tid == 0) {
            float t = 0.f;
            #pragma unroll
            for (int w = 0; w < TPB / 32; w++) t += redf[w];
            s_b[1] = t;
        }
        __syncthreads();
    }
    const float C1 = s_b[1];

    double accD = 0.0;

    // ---- label-dependent O(1)-per-row terms ----
    {
        const int gid = blockIdx.x * TPB + tid;
        if (gid < NROWS) {
            const int b = gid / 1023;
            const int t = gid - b * 1023;
            const int l = __ldg(&dec[b * SEQ + t + 1]);
            if (l != 0) {
                float pl = __ldg(p + (size_t)(b * SEQ + t) * VOCAB + l);
                float x  = sth[l] * inv01;
                accD += (double)(C1
                                 - x * logf(x)
                                 + (x + 0.9f) * logf(x + 0.9f)
                                 - 0.9f * logf(pl));
            }
        }
    }

    // ---- bulk: cross-row pipelined MUFU loop, streaming loads ----
    const bool hasTail = (tid < TAILQ);
    float thrAcc = 0.f;

    int row = blockIdx.x;
    if (row < NROWS) {
        const float4* cp = row_ptr(p, row);
        // preload all 8 quads of the first row
        float4 q0 = ldcs4(cp + tid);
        float4 q1 = ldcs4(cp + tid + 1 * TPB);
        float4 q2 = ldcs4(cp + tid + 2 * TPB);
        float4 q3 = ldcs4(cp + tid + 3 * TPB);
        float4 q4 = ldcs4(cp + tid + 4 * TPB);
        float4 q5 = ldcs4(cp + tid + 5 * TPB);
        float4 q6 = ldcs4(cp + tid + 6 * TPB);
        float4 q7;
        if (hasTail) q7 = ldcs4(cp + tid + 7 * TPB);

        while (true) {
            const int b   = row / 1023;
            const int lbl = __ldg(&dec[b * SEQ + (row - b * 1023) + 1]);

            float a0 = 0.f, a1 = 0.f;
            proc_quad(q0, sth4[tid          ], a0, a1);
            proc_quad(q1, sth4[tid + 1 * TPB], a0, a1);
            proc_quad(q2, sth4[tid + 2 * TPB], a0, a1);
            proc_quad(q3, sth4[tid + 3 * TPB], a0, a1);

            // refill head quads from the next row (re-read current on last iter)
            const int  nrow  = row + gridDim.x;
            const bool valid = (nrow < NROWS);
            const float4* np = valid ? row_ptr(p, nrow) : cp;
            q0 = ldcs4(np + tid);
            q1 = ldcs4(np + tid + 1 * TPB);
            q2 = ldcs4(np + tid + 2 * TPB);
            q3 = ldcs4(np + tid + 3 * TPB);

            proc_quad(q4, sth4[tid + 4 * TPB], a0, a1);
            proc_quad(q5, sth4[tid + 5 * TPB], a0, a1);
            proc_quad(q6, sth4[tid + 6 * TPB], a0, a1);
            if (hasTail) proc_quad(q7, sth4[tid + 7 * TPB], a0, a1);

            // refill tail quads from the next row
            q4 = ldcs4(np + tid + 4 * TPB);
            q5 = ldcs4(np + tid + 5 * TPB);
            q6 = ldcs4(np + tid + 6 * TPB);
            if (hasTail) q7 = ldcs4(np + tid + 7 * TPB);

            if (lbl != 0) thrAcc += a0 + a1;

            if (!valid) break;
            row = nrow;
            cp  = np;
        }
    }

    // fold: accD += -eps/usum * ln2 * thrAcc
    accD += (double)thrAcc * (-0.1 * 0.6931471805599453 / (double)usum);

    // ---- per-CTA reduction ----
    accD = warp_sum_d(accD);
    if ((tid & 31) == 0) redd[tid >> 5] = accD;
    __syncthreads();
    if (tid == 0) {
        double t = 0.0;
        #pragma unroll
        for (int w = 0; w < TPB / 32; w++) t += redd[w];
        g_part[blockIdx.x] = t;
        __threadfence();
        unsigned old = atomicAdd(&g_cnt, 1u);
        s_last = (old == gridDim.x - 1) ? 1 : 0;
    }
    __syncthreads();

    // ---- last CTA finalizes ----
    if (s_last) {
        double v = (tid < (int)gridDim.x) ? g_part[tid] : 0.0;
        v = warp_sum_d(v);
        if ((tid & 31) == 0) redd[tid >> 5] = v;
        __syncthreads();
        if (tid == 0) {
            double t = 0.0;
            #pragma unroll
            for (int w = 0; w < TPB / 32; w++) t += redd[w];
            out[0] = (float)(t / (double)NROWS);
            g_cnt = 0;                 // reset for next graph replay
        }
    }
}

extern "C" void kernel_launch(void* const* d_in, const int* in_sizes, int n_in,
                              void* d_out, int out_size) {
    const int*   dec = nullptr;
    const float* p   = nullptr;
    const float* th  = nullptr;
    for (int i = 0; i < n_in; ++i) {
        if (in_sizes[i] == 4 * SEQ)    dec = (const int*)d_in[i];
        else if (in_sizes[i] == VOCAB) th  = (const float*)d_in[i];
        else                           p   = (const float*)d_in[i];
    }

    cudaFuncSetAttribute(main_kernel,
                         cudaFuncAttributeMaxDynamicSharedMemorySize,
                         VOCAB * (int)sizeof(float));

    int sms = 0;
    cudaDeviceGetAttribute(&sms, cudaDevAttrMultiProcessorCount, 0);
    if (sms <= 0) sms = 148;
    if (sms > MAXCTA) sms = MAXCTA;

    main_kernel<<<sms, TPB, VOCAB * sizeof(float)>>>(p, dec, th, (float*)d_out);
}